// round 5
// baseline (speedup 1.0000x reference)
#include <cuda_runtime.h>
#include <math.h>

#define B_    4
#define NPTS  8192
#define KNN   9
#define TPB   256
#define QPB   256                 // queries per block
#define QT    2                   // queries per thread
#define SPLIT 4                   // candidate split
#define KTPB  ((QPB/QT)*SPLIT)    // 512 threads
#define CHUNK (NPTS/SPLIT)        // 2048 candidates per sub-scan
#define NPOINTS (B_*NPTS)         // 32768
#define NROWS   (NPOINTS*KNN)     // 294912
#define NB1     (NPOINTS/QPB)     // 128
#define NB3     (NROWS/TPB)       // 1152
#define EPS_BN  1e-5f

// ---- scratch (static device memory; no allocations) ----
__device__ int   g_nbr[(size_t)NPOINTS*KNN];
__device__ __align__(16) float g_h1[(size_t)NROWS*10];
__device__ __align__(16) float g_h2[(size_t)NROWS*10];
__device__ float g_part1[NB1*20];
__device__ float g_part2[NB3*20];
__device__ float g_coef1[20];
__device__ float g_coef2[20];

// ---- packed f32x2 helpers ----
__device__ __forceinline__ unsigned long long ffma2(unsigned long long a,
                                                    unsigned long long b,
                                                    unsigned long long c) {
    unsigned long long r;
    asm("fma.rn.f32x2 %0, %1, %2, %3;" : "=l"(r) : "l"(a), "l"(b), "l"(c));
    return r;
}
__device__ __forceinline__ unsigned long long pack2(float a, float b) {
    unsigned long long r;
    asm("mov.b64 %0, {%1, %2};" : "=l"(r) : "f"(a), "f"(b));
    return r;
}
__device__ __forceinline__ void unpack2(unsigned long long v, float& lo, float& hi) {
    asm("mov.b64 {%0, %1}, %2;" : "=f"(lo), "=f"(hi) : "l"(v));
}

// stable insert of (dv, di) into sorted-ascending (v[10], id[10]).
// equal values: existing entry stays earlier (candidates arrive in index order
// -> exact lax.top_k tie semantics).
__device__ __forceinline__ void ins_vi(float* v, int* id, float dv, int di) {
    float cv = dv; int ci = di;
    #pragma unroll
    for (int j = 0; j < 10; j++) {
        bool p = cv < v[j];
        float lo = fminf(v[j], cv);
        float hi = fmaxf(v[j], cv);
        int ni = p ? ci : id[j];
        int xi = p ? id[j] : ci;
        v[j] = lo; id[j] = ni; cv = hi; ci = xi;
    }
}

// =====================================================================
// Kernel A: kNN scan, single pass, inline ids, 2 queries/thread
// =====================================================================
__global__ void __launch_bounds__(KTPB, 1) k_knn(const float* __restrict__ x)
{
    extern __shared__ unsigned char smem_raw[];
    float* spx  = (float*)smem_raw;              // [NPTS]
    float* spy  = spx + NPTS;
    float* spz  = spy + NPTS;
    float* spw  = spz + NPTS;
    float* sMv  = spw + NPTS;                    // [(SPLIT-1)*QPB*10]
    int*   sMi  = (int*)(sMv + (SPLIT-1)*QPB*10);

    const int t  = threadIdx.x;
    const int g  = t & (QPB/QT - 1);             // query group 0..127
    const int s  = t / (QPB/QT);                 // sub-scan 0..3
    const int b  = blockIdx.x >> 5;
    const int q0 = (blockIdx.x & 31) * QPB + g*QT;   // within-batch query
    const float* xb = x + (size_t)b*NPTS*3;

    for (int i = t; i < NPTS; i += KTPB) {
        float px = xb[3*i+0], py = xb[3*i+1], pz = xb[3*i+2];
        spx[i] = px; spy[i] = py; spz[i] = pz;
        spw[i] = px*px + py*py + pz*pz;
    }
    __syncthreads();

    // two queries
    const float ax = spx[q0]*-2.f,   ay = spy[q0]*-2.f,   az = spz[q0]*-2.f;
    const float bx = spx[q0+1]*-2.f, by = spy[q0+1]*-2.f, bz = spz[q0+1]*-2.f;
    const unsigned long long pax = pack2(ax,ax), pay = pack2(ay,ay), paz = pack2(az,az);
    const unsigned long long pbx = pack2(bx,bx), pby = pack2(by,by), pbz = pack2(bz,bz);

    const ulonglong2* X2 = (const ulonglong2*)spx;
    const ulonglong2* Y2 = (const ulonglong2*)spy;
    const ulonglong2* Z2 = (const ulonglong2*)spz;
    const ulonglong2* W2 = (const ulonglong2*)spw;

    float v0[10], v1[10]; int i0[10], i1[10];
    #pragma unroll
    for (int j = 0; j < 10; j++) { v0[j]=3.4e38f; v1[j]=3.4e38f; i0[j]=-1; i1[j]=-1; }

    const int mbase = s * CHUNK;
    #pragma unroll 1
    for (int m0 = mbase; m0 < mbase + CHUNK; m0 += 8) {
        const int e = m0 >> 2;
        ulonglong2 xa = X2[e], xb2 = X2[e+1];
        ulonglong2 ya = Y2[e], yb = Y2[e+1];
        ulonglong2 za = Z2[e], zb = Z2[e+1];
        ulonglong2 wa = W2[e], wb = W2[e+1];

        // ---- query 0 ----
        {
            unsigned long long d01 = ffma2(xa.x, pax, wa.x);
            unsigned long long d23 = ffma2(xa.y, pax, wa.y);
            unsigned long long d45 = ffma2(xb2.x, pax, wb.x);
            unsigned long long d67 = ffma2(xb2.y, pax, wb.y);
            d01 = ffma2(ya.x, pay, d01);  d23 = ffma2(ya.y, pay, d23);
            d45 = ffma2(yb.x, pay, d45);  d67 = ffma2(yb.y, pay, d67);
            d01 = ffma2(za.x, paz, d01);  d23 = ffma2(za.y, paz, d23);
            d45 = ffma2(zb.x, paz, d45);  d67 = ffma2(zb.y, paz, d67);
            float d0,d1,d2,d3,d4,d5,d6,d7;
            unpack2(d01,d0,d1); unpack2(d23,d2,d3);
            unpack2(d45,d4,d5); unpack2(d67,d6,d7);
            float mn = fminf(fminf(fminf(d0,d1), fminf(d2,d3)),
                             fminf(fminf(d4,d5), fminf(d6,d7)));
            if (mn < v0[9]) {
                if (d0 < v0[9]) ins_vi(v0,i0,d0,m0+0);
                if (d1 < v0[9]) ins_vi(v0,i0,d1,m0+1);
                if (d2 < v0[9]) ins_vi(v0,i0,d2,m0+2);
                if (d3 < v0[9]) ins_vi(v0,i0,d3,m0+3);
                if (d4 < v0[9]) ins_vi(v0,i0,d4,m0+4);
                if (d5 < v0[9]) ins_vi(v0,i0,d5,m0+5);
                if (d6 < v0[9]) ins_vi(v0,i0,d6,m0+6);
                if (d7 < v0[9]) ins_vi(v0,i0,d7,m0+7);
            }
        }
        // ---- query 1 ----
        {
            unsigned long long d01 = ffma2(xa.x, pbx, wa.x);
            unsigned long long d23 = ffma2(xa.y, pbx, wa.y);
            unsigned long long d45 = ffma2(xb2.x, pbx, wb.x);
            unsigned long long d67 = ffma2(xb2.y, pbx, wb.y);
            d01 = ffma2(ya.x, pby, d01);  d23 = ffma2(ya.y, pby, d23);
            d45 = ffma2(yb.x, pby, d45);  d67 = ffma2(yb.y, pby, d67);
            d01 = ffma2(za.x, pbz, d01);  d23 = ffma2(za.y, pbz, d23);
            d45 = ffma2(zb.x, pbz, d45);  d67 = ffma2(zb.y, pbz, d67);
            float d0,d1,d2,d3,d4,d5,d6,d7;
            unpack2(d01,d0,d1); unpack2(d23,d2,d3);
            unpack2(d45,d4,d5); unpack2(d67,d6,d7);
            float mn = fminf(fminf(fminf(d0,d1), fminf(d2,d3)),
                             fminf(fminf(d4,d5), fminf(d6,d7)));
            if (mn < v1[9]) {
                if (d0 < v1[9]) ins_vi(v1,i1,d0,m0+0);
                if (d1 < v1[9]) ins_vi(v1,i1,d1,m0+1);
                if (d2 < v1[9]) ins_vi(v1,i1,d2,m0+2);
                if (d3 < v1[9]) ins_vi(v1,i1,d3,m0+3);
                if (d4 < v1[9]) ins_vi(v1,i1,d4,m0+4);
                if (d5 < v1[9]) ins_vi(v1,i1,d5,m0+5);
                if (d6 < v1[9]) ins_vi(v1,i1,d6,m0+6);
                if (d7 < v1[9]) ins_vi(v1,i1,d7,m0+7);
            }
        }
    }

    // ---- merge sub-scans (index order s=0,1,2,3 preserves tie stability) --
    const int ql0 = g*QT, ql1 = g*QT + 1;
    if (s > 0) {
        const int base0 = ((s-1)*QPB + ql0)*10;
        const int base1 = ((s-1)*QPB + ql1)*10;
        #pragma unroll
        for (int j = 0; j < 10; j++) {
            sMv[base0 + j] = v0[j];  sMi[base0 + j] = i0[j];
            sMv[base1 + j] = v1[j];  sMi[base1 + j] = i1[j];
        }
    }
    __syncthreads();
    if (s == 0) {
        #pragma unroll 1
        for (int ss = 0; ss < SPLIT-1; ss++) {
            const int base0 = (ss*QPB + ql0)*10;
            const int base1 = (ss*QPB + ql1)*10;
            #pragma unroll
            for (int j = 0; j < 10; j++) {
                float mv = sMv[base0 + j];
                if (mv < v0[9]) ins_vi(v0, i0, mv, sMi[base0 + j]);
            }
            #pragma unroll
            for (int j = 0; j < 10; j++) {
                float mv = sMv[base1 + j];
                if (mv < v1[9]) ins_vi(v1, i1, mv, sMi[base1 + j]);
            }
        }
        // entry 0 is the "self" column dropped by the reference; keep 1..9
        int* d0p = g_nbr + (size_t)(b*NPTS + q0)*KNN;
        int* d1p = g_nbr + (size_t)(b*NPTS + q0 + 1)*KNN;
        #pragma unroll
        for (int j = 1; j < 10; j++) { d0p[j-1] = i0[j]; d1p[j-1] = i1[j]; }
    }
}

// =====================================================================
// Kernel B: angular features + GEMM1 + stats1
// =====================================================================
__global__ void __launch_bounds__(TPB) k_feat(const float* __restrict__ x,
                                              const float* __restrict__ W1,
                                              const float* __restrict__ b1)
{
    __shared__ float sW1[70], sB1[10], sRed[(TPB/32)*20];
    const int t = threadIdx.x;
    if (t < 70) sW1[t] = W1[t];
    if (t < 10) sB1[t] = b1[t];
    __syncthreads();

    const int p = blockIdx.x*TPB + t;
    const int b = p / NPTS;
    const int n = p % NPTS;
    const float* xb = x + (size_t)b*NPTS*3;
    const float qx = xb[3*n+0], qy = xb[3*n+1], qz = xb[3*n+2];

    const int* ids = g_nbr + (size_t)p*KNN;
    float rx[KNN], ry[KNN], rz[KNN], ph[KNN];
    #pragma unroll
    for (int j = 0; j < KNN; j++) {
        int id = ids[j];
        rx[j] = xb[3*id+0] - qx;
        ry[j] = xb[3*id+1] - qy;
        rz[j] = xb[3*id+2] - qz;
        ph[j] = atan2f(ry[j], rx[j]);
    }

    #pragma unroll
    for (int pass = 0; pass < KNN-1; pass++) {
        #pragma unroll
        for (int j = 0; j < KNN-1; j++) {
            if (j < KNN-1-pass) {
                if (ph[j+1] < ph[j]) {
                    float tt;
                    tt = ph[j]; ph[j] = ph[j+1]; ph[j+1] = tt;
                    tt = rx[j]; rx[j] = rx[j+1]; rx[j+1] = tt;
                    tt = ry[j]; ry[j] = ry[j+1]; ry[j+1] = tt;
                    tt = rz[j]; rz[j] = rz[j+1]; rz[j+1] = tt;
                }
            }
        }
    }

    float sum[10], sq[10];
    #pragma unroll
    for (int c = 0; c < 10; c++) { sum[c] = 0.f; sq[c] = 0.f; }

    float sgn = 1.f;
    const size_t rowbase = (size_t)p * KNN * 10;
    #pragma unroll
    for (int i = 0; i < KNN; i++) {
        const int i2 = (i+1) % KNN;
        float v1x = rx[i],  v1y = ry[i],  v1z = rz[i];
        float v2x = rx[i2], v2y = ry[i2], v2z = rz[i2];
        float cx = 0.5f*(v1x+v2x), cy = 0.5f*(v1y+v2y), cz = 0.5f*(v1z+v2z);
        float nx = v1y*v2z - v1z*v2y;
        float ny = v1z*v2x - v1x*v2z;
        float nz = v1x*v2y - v1y*v2x;
        float nrm = sqrtf(nx*nx + ny*ny + nz*nz);
        float inv = 1.f/(nrm + 1e-6f);
        nx *= inv; ny *= inv; nz *= inv;
        if (i == 0) sgn = (nx > 0.f) ? 1.f : -1.f;
        nx *= sgn; ny *= sgn; nz *= sgn;
        float pos7 = (nx*cx + ny*cy + nz*cz) * 0.57735026918962576f;

        float f[7] = {cx, cy, cz, nx, ny, nz, pos7};
        #pragma unroll
        for (int c = 0; c < 10; c++) {
            float h = sB1[c];
            #pragma unroll
            for (int ff = 0; ff < 7; ff++) h = fmaf(f[ff], sW1[ff*10 + c], h);
            g_h1[rowbase + i*10 + c] = h;
            sum[c] += h;
            sq[c]  = fmaf(h, h, sq[c]);
        }
    }

    #pragma unroll
    for (int c = 0; c < 10; c++) {
        #pragma unroll
        for (int o = 16; o > 0; o >>= 1) {
            sum[c] += __shfl_down_sync(0xffffffffu, sum[c], o);
            sq[c]  += __shfl_down_sync(0xffffffffu, sq[c],  o);
        }
    }
    const int warp = t >> 5, lane = t & 31;
    if (lane == 0) {
        #pragma unroll
        for (int c = 0; c < 10; c++) {
            sRed[warp*20 + c]      = sum[c];
            sRed[warp*20 + 10 + c] = sq[c];
        }
    }
    __syncthreads();
    if (t < 20) {
        float acc = 0.f;
        #pragma unroll
        for (int w = 0; w < TPB/32; w++) acc += sRed[w*20 + t];
        g_part1[blockIdx.x*20 + t] = acc;
    }
}

// =====================================================================
// Parallel BN-stats finalize
// =====================================================================
__device__ __forceinline__ void fin_body(const float* __restrict__ part, int nblk,
                                         const float* __restrict__ g,
                                         const float* __restrict__ be,
                                         float* __restrict__ coef)
{
    __shared__ float red[32*20];
    __shared__ float tot[20];
    const int t = threadIdx.x;
    const int c = t % 20, sub = t / 20;
    float acc = 0.f;
    for (int k = sub; k < nblk; k += 32) acc += part[k*20 + c];
    red[sub*20 + c] = acc;
    __syncthreads();
    if (t < 20) {
        float s = 0.f;
        #pragma unroll
        for (int w = 0; w < 32; w++) s += red[w*20 + t];
        tot[t] = s;
    }
    __syncthreads();
    if (t < 10) {
        float mu  = tot[t] / (float)NROWS;
        float var = tot[10 + t] / (float)NROWS - mu*mu;
        float a   = g[t] * rsqrtf(var + EPS_BN);
        coef[t]      = a;
        coef[10 + t] = be[t] - mu*a;
    }
}

__global__ void k_fin1(const float* __restrict__ g1, const float* __restrict__ be1)
{ fin_body(g_part1, NB1, g1, be1, g_coef1); }

__global__ void k_fin2(const float* __restrict__ g2, const float* __restrict__ be2)
{ fin_body(g_part2, NB3, g2, be2, g_coef2); }

// =====================================================================
// Kernel 3: BN1 + relu + GEMM2 + stats2  (float2 I/O)
// =====================================================================
__global__ void __launch_bounds__(TPB) k_mlp2(const float* __restrict__ W2,
                                              const float* __restrict__ b2)
{
    __shared__ float sW2[100], sB2[10], sA[10], sC[10], sRed[(TPB/32)*20];
    const int t = threadIdx.x;
    if (t < 100) sW2[t] = W2[t];
    if (t < 10) { sB2[t] = b2[t]; sA[t] = g_coef1[t]; sC[t] = g_coef1[10+t]; }
    __syncthreads();

    const size_t row = (size_t)blockIdx.x*TPB + t;
    const float2* src2 = (const float2*)(g_h1 + row*10);

    float h[10];
    #pragma unroll
    for (int c = 0; c < 5; c++) {
        float2 v = src2[c];
        h[2*c+0] = fmaxf(fmaf(v.x, sA[2*c+0], sC[2*c+0]), 0.f);
        h[2*c+1] = fmaxf(fmaf(v.y, sA[2*c+1], sC[2*c+1]), 0.f);
    }

    float sum[10], sq[10];
    float2* dst2 = (float2*)(g_h2 + row*10);
    #pragma unroll
    for (int c2 = 0; c2 < 10; c2++) {
        float z = sB2[c2];
        #pragma unroll
        for (int c = 0; c < 10; c++) z = fmaf(h[c], sW2[c*10 + c2], z);
        sum[c2] = z;
        sq[c2]  = z*z;
    }
    #pragma unroll
    for (int c = 0; c < 5; c++) dst2[c] = make_float2(sum[2*c], sum[2*c+1]);

    #pragma unroll
    for (int c = 0; c < 10; c++) {
        #pragma unroll
        for (int o = 16; o > 0; o >>= 1) {
            sum[c] += __shfl_down_sync(0xffffffffu, sum[c], o);
            sq[c]  += __shfl_down_sync(0xffffffffu, sq[c],  o);
        }
    }
    const int warp = t >> 5, lane = t & 31;
    if (lane == 0) {
        #pragma unroll
        for (int c = 0; c < 10; c++) {
            sRed[warp*20 + c]      = sum[c];
            sRed[warp*20 + 10 + c] = sq[c];
        }
    }
    __syncthreads();
    if (t < 20) {
        float acc = 0.f;
        #pragma unroll
        for (int w = 0; w < TPB/32; w++) acc += sRed[w*20 + t];
        g_part2[blockIdx.x*20 + t] = acc;
    }
}

// =====================================================================
// Kernel 5: BN2 + relu + max over k  (float2 I/O)
// =====================================================================
__global__ void __launch_bounds__(TPB) k_out(float* __restrict__ out)
{
    __shared__ float sA[10], sC[10];
    if (threadIdx.x < 10) { sA[threadIdx.x] = g_coef2[threadIdx.x]; sC[threadIdx.x] = g_coef2[10+threadIdx.x]; }
    __syncthreads();

    const size_t p = (size_t)blockIdx.x*TPB + threadIdx.x;
    const float2* src2 = (const float2*)(g_h2 + p*KNN*10);

    float mx[10];
    #pragma unroll
    for (int c = 0; c < 10; c++) mx[c] = 0.f;

    #pragma unroll
    for (int i = 0; i < KNN; i++) {
        #pragma unroll
        for (int c = 0; c < 5; c++) {
            float2 v = src2[i*5 + c];
            mx[2*c+0] = fmaxf(mx[2*c+0], fmaxf(fmaf(v.x, sA[2*c+0], sC[2*c+0]), 0.f));
            mx[2*c+1] = fmaxf(mx[2*c+1], fmaxf(fmaf(v.y, sA[2*c+1], sC[2*c+1]), 0.f));
        }
    }
    float2* o2 = (float2*)(out + p*10);
    #pragma unroll
    for (int c = 0; c < 5; c++) o2[c] = make_float2(mx[2*c], mx[2*c+1]);
}

// =====================================================================
extern "C" void kernel_launch(void* const* d_in, const int* in_sizes, int n_in,
                              void* d_out, int out_size)
{
    const float* x   = (const float*)d_in[0];
    const float* W1  = (const float*)d_in[1];
    const float* b1  = (const float*)d_in[2];
    const float* g1  = (const float*)d_in[3];
    const float* be1 = (const float*)d_in[4];
    const float* W2  = (const float*)d_in[5];
    const float* b2  = (const float*)d_in[6];
    const float* g2  = (const float*)d_in[7];
    const float* be2 = (const float*)d_in[8];
    float* out = (float*)d_out;

    const size_t smemA = (size_t)4*NPTS*sizeof(float)
                       + (size_t)(SPLIT-1)*QPB*10*(sizeof(float)+sizeof(int));
    cudaFuncSetAttribute(k_knn, cudaFuncAttributeMaxDynamicSharedMemorySize, (int)smemA);

    k_knn<<<NB1, KTPB, smemA>>>(x);
    k_feat<<<NB1, TPB>>>(x, W1, b1);
    k_fin1<<<1, 640>>>(g1, be1);
    k_mlp2<<<NB3, TPB>>>(W2, b2);
    k_fin2<<<1, 640>>>(g2, be2);
    k_out<<<NPOINTS/TPB, TPB>>>(out);
}

// round 6
// speedup vs baseline: 1.1883x; 1.1883x over previous
#include <cuda_runtime.h>
#include <math.h>

#define B_    4
#define NPTS  8192
#define KNN   9
#define TPB   256
#define QPB   256                 // queries per block
#define QT    2                   // queries per thread
#define SPLIT 4                   // candidate split
#define GRP   (QPB/QT)            // 128 query groups
#define KTPB  (GRP*SPLIT)         // 512 threads
#define CHUNK (NPTS/SPLIT)        // 2048 candidates per sub-scan
#define CAP   12                  // phase-2 list capacity per (query,quarter)
#define NPOINTS (B_*NPTS)         // 32768
#define NROWS   (NPOINTS*KNN)     // 294912
#define NB1     (NPOINTS/QPB)     // 128
#define NB3     (NROWS/TPB)       // 1152
#define EPS_BN  1e-5f

// ---- scratch (static device memory; no allocations) ----
__device__ int   g_nbr[(size_t)NPOINTS*KNN];
__device__ __align__(16) float g_h1[(size_t)NROWS*10];
__device__ __align__(16) float g_h2[(size_t)NROWS*10];
__device__ float g_part1[NB1*20];
__device__ float g_part2[NB3*20];
__device__ float g_coef1[20];
__device__ float g_coef2[20];

// ---- packed f32x2 helpers ----
__device__ __forceinline__ unsigned long long ffma2(unsigned long long a,
                                                    unsigned long long b,
                                                    unsigned long long c) {
    unsigned long long r;
    asm("fma.rn.f32x2 %0, %1, %2, %3;" : "=l"(r) : "l"(a), "l"(b), "l"(c));
    return r;
}
__device__ __forceinline__ unsigned long long pack2(float a, float b) {
    unsigned long long r;
    asm("mov.b64 %0, {%1, %2};" : "=l"(r) : "f"(a), "f"(b));
    return r;
}
__device__ __forceinline__ void unpack2(unsigned long long v, float& lo, float& hi) {
    asm("mov.b64 {%0, %1}, %2;" : "=f"(lo), "=f"(hi) : "l"(v));
}

// branchless insert of one value into sorted-ascending s[0..9] (values only)
#define CHAIN_INSERT(sarr, val) do {                 \
    float _c = (val);                                \
    _Pragma("unroll")                                \
    for (int _j = 0; _j < 10; _j++) {                \
        float _lo = fminf(sarr[_j], _c);             \
        _c = fmaxf(sarr[_j], _c);                    \
        sarr[_j] = _lo;                              \
    }                                                \
} while (0)

// =====================================================================
// Kernel A: kNN scan — 2 phases, 2 queries/thread, 4-way candidate split
// =====================================================================
__global__ void __launch_bounds__(KTPB, 1) k_knn(const float* __restrict__ x)
{
    extern __shared__ unsigned char smem_raw[];
    float* spx  = (float*)smem_raw;              // [NPTS]
    float* spy  = spx + NPTS;
    float* spz  = spy + NPTS;
    float* spw  = spz + NPTS;
    float* sMv  = spw + NPTS;                    // [(SPLIT-1)*QPB*10]
    float* sThr = sMv + (SPLIT-1)*QPB*10;        // [QPB]
    int*   sList = (int*)(sThr + QPB);           // [KTPB*QT*CAP]
    int*   sCnt  = sList + KTPB*QT*CAP;          // [KTPB*QT]

    const int t  = threadIdx.x;
    const int g  = t & (GRP-1);                  // query group 0..127
    const int s  = t >> 7;                       // quarter 0..3
    const int b  = blockIdx.x >> 5;
    const int q0 = (blockIdx.x & 31) * QPB + g*QT;
    const int ql0 = g*QT, ql1 = g*QT + 1;
    const float* xb = x + (size_t)b*NPTS*3;

    for (int i = t; i < NPTS; i += KTPB) {
        float px = xb[3*i+0], py = xb[3*i+1], pz = xb[3*i+2];
        spx[i] = px; spy[i] = py; spz[i] = pz;
        spw[i] = px*px + py*py + pz*pz;
    }
    __syncthreads();

    const float ax = spx[q0]*-2.f,   ay = spy[q0]*-2.f,   az = spz[q0]*-2.f;
    const float bx = spx[q0+1]*-2.f, by = spy[q0+1]*-2.f, bz = spz[q0+1]*-2.f;
    const unsigned long long pax = pack2(ax,ax), pay = pack2(ay,ay), paz = pack2(az,az);
    const unsigned long long pbx = pack2(bx,bx), pby = pack2(by,by), pbz = pack2(bz,bz);

    const ulonglong2* X2 = (const ulonglong2*)spx;
    const ulonglong2* Y2 = (const ulonglong2*)spy;
    const ulonglong2* Z2 = (const ulonglong2*)spz;
    const ulonglong2* W2 = (const ulonglong2*)spw;

    // ---------------- phase 1: values-only top-10 (both queries) --------
    float v0[10], v1[10];
    #pragma unroll
    for (int j = 0; j < 10; j++) { v0[j] = 3.4e38f; v1[j] = 3.4e38f; }

    const int mbase = s * CHUNK;
    #pragma unroll 1
    for (int m0 = mbase; m0 < mbase + CHUNK; m0 += 8) {
        const int e = m0 >> 2;
        ulonglong2 xa = X2[e], xb2 = X2[e+1];
        ulonglong2 ya = Y2[e], yb = Y2[e+1];
        ulonglong2 za = Z2[e], zb = Z2[e+1];
        ulonglong2 wa = W2[e], wb = W2[e+1];

        // query 0 distances
        unsigned long long a01 = ffma2(xa.x, pax, wa.x);
        unsigned long long a23 = ffma2(xa.y, pax, wa.y);
        unsigned long long a45 = ffma2(xb2.x, pax, wb.x);
        unsigned long long a67 = ffma2(xb2.y, pax, wb.y);
        a01 = ffma2(ya.x, pay, a01);  a23 = ffma2(ya.y, pay, a23);
        a45 = ffma2(yb.x, pay, a45);  a67 = ffma2(yb.y, pay, a67);
        a01 = ffma2(za.x, paz, a01);  a23 = ffma2(za.y, paz, a23);
        a45 = ffma2(zb.x, paz, a45);  a67 = ffma2(zb.y, paz, a67);
        // query 1 distances (independent chain -> ILP)
        unsigned long long b01 = ffma2(xa.x, pbx, wa.x);
        unsigned long long b23 = ffma2(xa.y, pbx, wa.y);
        unsigned long long b45 = ffma2(xb2.x, pbx, wb.x);
        unsigned long long b67 = ffma2(xb2.y, pbx, wb.y);
        b01 = ffma2(ya.x, pby, b01);  b23 = ffma2(ya.y, pby, b23);
        b45 = ffma2(yb.x, pby, b45);  b67 = ffma2(yb.y, pby, b67);
        b01 = ffma2(za.x, pbz, b01);  b23 = ffma2(za.y, pbz, b23);
        b45 = ffma2(zb.x, pbz, b45);  b67 = ffma2(zb.y, pbz, b67);

        float e0,e1,e2,e3,e4,e5,e6,e7;
        unpack2(a01,e0,e1); unpack2(a23,e2,e3);
        unpack2(a45,e4,e5); unpack2(a67,e6,e7);
        float f0,f1,f2,f3,f4,f5,f6,f7;
        unpack2(b01,f0,f1); unpack2(b23,f2,f3);
        unpack2(b45,f4,f5); unpack2(b67,f6,f7);

        float mnA = fminf(fminf(fminf(e0,e1), fminf(e2,e3)),
                          fminf(fminf(e4,e5), fminf(e6,e7)));
        float mnB = fminf(fminf(fminf(f0,f1), fminf(f2,f3)),
                          fminf(fminf(f4,f5), fminf(f6,f7)));
        if (mnA < v0[9] || mnB < v1[9]) {
            if (e0 < v0[9]) CHAIN_INSERT(v0, e0);
            if (e1 < v0[9]) CHAIN_INSERT(v0, e1);
            if (e2 < v0[9]) CHAIN_INSERT(v0, e2);
            if (e3 < v0[9]) CHAIN_INSERT(v0, e3);
            if (e4 < v0[9]) CHAIN_INSERT(v0, e4);
            if (e5 < v0[9]) CHAIN_INSERT(v0, e5);
            if (e6 < v0[9]) CHAIN_INSERT(v0, e6);
            if (e7 < v0[9]) CHAIN_INSERT(v0, e7);
            if (f0 < v1[9]) CHAIN_INSERT(v1, f0);
            if (f1 < v1[9]) CHAIN_INSERT(v1, f1);
            if (f2 < v1[9]) CHAIN_INSERT(v1, f2);
            if (f3 < v1[9]) CHAIN_INSERT(v1, f3);
            if (f4 < v1[9]) CHAIN_INSERT(v1, f4);
            if (f5 < v1[9]) CHAIN_INSERT(v1, f5);
            if (f6 < v1[9]) CHAIN_INSERT(v1, f6);
            if (f7 < v1[9]) CHAIN_INSERT(v1, f7);
        }
    }

    // ---------------- merge quarters -> exact thresholds ----------------
    if (s > 0) {
        const int base0 = ((s-1)*QPB + ql0)*10;
        const int base1 = ((s-1)*QPB + ql1)*10;
        #pragma unroll
        for (int j = 0; j < 10; j++) { sMv[base0+j] = v0[j]; sMv[base1+j] = v1[j]; }
    }
    __syncthreads();
    float gmin0 = 0.f, gmin1 = 0.f;
    if (s == 0) {
        #pragma unroll 1
        for (int ss = 0; ss < SPLIT-1; ss++) {
            const int base0 = (ss*QPB + ql0)*10;
            const int base1 = (ss*QPB + ql1)*10;
            #pragma unroll
            for (int j = 0; j < 10; j++) {
                float mv = sMv[base0+j];
                if (mv < v0[9]) CHAIN_INSERT(v0, mv);
            }
            #pragma unroll
            for (int j = 0; j < 10; j++) {
                float mv = sMv[base1+j];
                if (mv < v1[9]) CHAIN_INSERT(v1, mv);
            }
        }
        gmin0 = v0[0]; gmin1 = v1[0];
        sThr[ql0] = v0[9];
        sThr[ql1] = v1[9];
    }
    __syncthreads();
    const float thr0 = sThr[ql0];
    const float thr1 = sThr[ql1];

    // ---------------- phase 2: collect qualifying ids (index order) -----
    int cnt0 = 0, cnt1 = 0;
    int* list0 = sList + (t*QT + 0)*CAP;
    int* list1 = sList + (t*QT + 1)*CAP;
    #pragma unroll 1
    for (int m0 = mbase; m0 < mbase + CHUNK; m0 += 8) {
        const int e = m0 >> 2;
        ulonglong2 xa = X2[e], xb2 = X2[e+1];
        ulonglong2 ya = Y2[e], yb = Y2[e+1];
        ulonglong2 za = Z2[e], zb = Z2[e+1];
        ulonglong2 wa = W2[e], wb = W2[e+1];

        unsigned long long a01 = ffma2(xa.x, pax, wa.x);
        unsigned long long a23 = ffma2(xa.y, pax, wa.y);
        unsigned long long a45 = ffma2(xb2.x, pax, wb.x);
        unsigned long long a67 = ffma2(xb2.y, pax, wb.y);
        a01 = ffma2(ya.x, pay, a01);  a23 = ffma2(ya.y, pay, a23);
        a45 = ffma2(yb.x, pay, a45);  a67 = ffma2(yb.y, pay, a67);
        a01 = ffma2(za.x, paz, a01);  a23 = ffma2(za.y, paz, a23);
        a45 = ffma2(zb.x, paz, a45);  a67 = ffma2(zb.y, paz, a67);
        unsigned long long b01 = ffma2(xa.x, pbx, wa.x);
        unsigned long long b23 = ffma2(xa.y, pbx, wa.y);
        unsigned long long b45 = ffma2(xb2.x, pbx, wb.x);
        unsigned long long b67 = ffma2(xb2.y, pbx, wb.y);
        b01 = ffma2(ya.x, pby, b01);  b23 = ffma2(ya.y, pby, b23);
        b45 = ffma2(yb.x, pby, b45);  b67 = ffma2(yb.y, pby, b67);
        b01 = ffma2(za.x, pbz, b01);  b23 = ffma2(za.y, pbz, b23);
        b45 = ffma2(zb.x, pbz, b45);  b67 = ffma2(zb.y, pbz, b67);

        float ea[8], fb[8];
        unpack2(a01,ea[0],ea[1]); unpack2(a23,ea[2],ea[3]);
        unpack2(a45,ea[4],ea[5]); unpack2(a67,ea[6],ea[7]);
        unpack2(b01,fb[0],fb[1]); unpack2(b23,fb[2],fb[3]);
        unpack2(b45,fb[4],fb[5]); unpack2(b67,fb[6],fb[7]);

        float mnA = fminf(fminf(fminf(ea[0],ea[1]), fminf(ea[2],ea[3])),
                          fminf(fminf(ea[4],ea[5]), fminf(ea[6],ea[7])));
        float mnB = fminf(fminf(fminf(fb[0],fb[1]), fminf(fb[2],fb[3])),
                          fminf(fminf(fb[4],fb[5]), fminf(fb[6],fb[7])));
        if (mnA <= thr0 || mnB <= thr1) {
            #pragma unroll
            for (int u = 0; u < 8; u++) {
                if (ea[u] <= thr0 && cnt0 < CAP) { list0[cnt0] = m0 + u; cnt0++; }
            }
            #pragma unroll
            for (int u = 0; u < 8; u++) {
                if (fb[u] <= thr1 && cnt1 < CAP) { list1[cnt1] = m0 + u; cnt1++; }
            }
        }
    }
    sCnt[t*QT + 0] = cnt0;
    sCnt[t*QT + 1] = cnt1;
    __syncthreads();

    // ---------------- selection (quarter-0 threads, thread-local) -------
    if (s == 0) {
        #pragma unroll 1
        for (int lq = 0; lq < QT; lq++) {
            const float thr = lq ? thr1 : thr0;
            const float gmn = lq ? gmin1 : gmin0;
            const float nx = lq ? bx : ax;
            const float ny = lq ? by : ay;
            const float nz = lq ? bz : az;
            int fin[10]; int np = 0;
            // pass A: strictly below threshold, index order across quarters
            #pragma unroll 1
            for (int h = 0; h < SPLIT; h++) {
                const int th2 = (h*GRP + g)*QT + lq;
                const int* L = sList + th2*CAP;
                const int  C = sCnt[th2];
                for (int j = 0; j < C; j++) {
                    int id = L[j];
                    float v = fmaf(spx[id], nx, spw[id]);
                    v = fmaf(spy[id], ny, v);
                    v = fmaf(spz[id], nz, v);
                    if (v < thr && np < 10) { fin[np] = id; np++; }
                }
            }
            // pass B: ties at threshold, index order
            #pragma unroll 1
            for (int h = 0; h < SPLIT; h++) {
                const int th2 = (h*GRP + g)*QT + lq;
                const int* L = sList + th2*CAP;
                const int  C = sCnt[th2];
                for (int j = 0; j < C; j++) {
                    int id = L[j];
                    float v = fmaf(spx[id], nx, spw[id]);
                    v = fmaf(spy[id], ny, v);
                    v = fmaf(spz[id], nz, v);
                    if (v == thr && np < 10) { fin[np] = id; np++; }
                }
            }
            // drop the entry matching the global min (self)
            int pos = 0; bool found = false;
            #pragma unroll
            for (int j = 0; j < 10; j++) {
                int id = fin[j];
                float v = fmaf(spx[id], nx, spw[id]);
                v = fmaf(spy[id], ny, v);
                v = fmaf(spz[id], nz, v);
                if (!found && v == gmn) { pos = j; found = true; }
            }
            int* dst = g_nbr + (size_t)(b*NPTS + q0 + lq)*KNN;
            #pragma unroll
            for (int j = 1; j < 10; j++) {
                int srcj = (j-1) + ((j-1) >= pos ? 1 : 0);
                dst[j-1] = fin[srcj];
            }
        }
    }
}

// =====================================================================
// Kernel B: angular features + GEMM1 + stats1
// =====================================================================
__global__ void __launch_bounds__(TPB) k_feat(const float* __restrict__ x,
                                              const float* __restrict__ W1,
                                              const float* __restrict__ b1)
{
    __shared__ float sW1[70], sB1[10], sRed[(TPB/32)*20];
    const int t = threadIdx.x;
    if (t < 70) sW1[t] = W1[t];
    if (t < 10) sB1[t] = b1[t];
    __syncthreads();

    const int p = blockIdx.x*TPB + t;
    const int b = p / NPTS;
    const int n = p % NPTS;
    const float* xb = x + (size_t)b*NPTS*3;
    const float qx = xb[3*n+0], qy = xb[3*n+1], qz = xb[3*n+2];

    const int* ids = g_nbr + (size_t)p*KNN;
    float rx[KNN], ry[KNN], rz[KNN], ph[KNN];
    #pragma unroll
    for (int j = 0; j < KNN; j++) {
        int id = ids[j];
        rx[j] = xb[3*id+0] - qx;
        ry[j] = xb[3*id+1] - qy;
        rz[j] = xb[3*id+2] - qz;
        ph[j] = atan2f(ry[j], rx[j]);
    }

    #pragma unroll
    for (int pass = 0; pass < KNN-1; pass++) {
        #pragma unroll
        for (int j = 0; j < KNN-1; j++) {
            if (j < KNN-1-pass) {
                if (ph[j+1] < ph[j]) {
                    float tt;
                    tt = ph[j]; ph[j] = ph[j+1]; ph[j+1] = tt;
                    tt = rx[j]; rx[j] = rx[j+1]; rx[j+1] = tt;
                    tt = ry[j]; ry[j] = ry[j+1]; ry[j+1] = tt;
                    tt = rz[j]; rz[j] = rz[j+1]; rz[j+1] = tt;
                }
            }
        }
    }

    float sum[10], sq[10];
    #pragma unroll
    for (int c = 0; c < 10; c++) { sum[c] = 0.f; sq[c] = 0.f; }

    float sgn = 1.f;
    const size_t rowbase = (size_t)p * KNN * 10;
    #pragma unroll
    for (int i = 0; i < KNN; i++) {
        const int i2 = (i+1) % KNN;
        float v1x = rx[i],  v1y = ry[i],  v1z = rz[i];
        float v2x = rx[i2], v2y = ry[i2], v2z = rz[i2];
        float cx = 0.5f*(v1x+v2x), cy = 0.5f*(v1y+v2y), cz = 0.5f*(v1z+v2z);
        float nx = v1y*v2z - v1z*v2y;
        float ny = v1z*v2x - v1x*v2z;
        float nz = v1x*v2y - v1y*v2x;
        float nrm = sqrtf(nx*nx + ny*ny + nz*nz);
        float inv = 1.f/(nrm + 1e-6f);
        nx *= inv; ny *= inv; nz *= inv;
        if (i == 0) sgn = (nx > 0.f) ? 1.f : -1.f;
        nx *= sgn; ny *= sgn; nz *= sgn;
        float pos7 = (nx*cx + ny*cy + nz*cz) * 0.57735026918962576f;

        float f[7] = {cx, cy, cz, nx, ny, nz, pos7};
        #pragma unroll
        for (int c = 0; c < 10; c++) {
            float h = sB1[c];
            #pragma unroll
            for (int ff = 0; ff < 7; ff++) h = fmaf(f[ff], sW1[ff*10 + c], h);
            g_h1[rowbase + i*10 + c] = h;
            sum[c] += h;
            sq[c]  = fmaf(h, h, sq[c]);
        }
    }

    #pragma unroll
    for (int c = 0; c < 10; c++) {
        #pragma unroll
        for (int o = 16; o > 0; o >>= 1) {
            sum[c] += __shfl_down_sync(0xffffffffu, sum[c], o);
            sq[c]  += __shfl_down_sync(0xffffffffu, sq[c],  o);
        }
    }
    const int warp = t >> 5, lane = t & 31;
    if (lane == 0) {
        #pragma unroll
        for (int c = 0; c < 10; c++) {
            sRed[warp*20 + c]      = sum[c];
            sRed[warp*20 + 10 + c] = sq[c];
        }
    }
    __syncthreads();
    if (t < 20) {
        float acc = 0.f;
        #pragma unroll
        for (int w = 0; w < TPB/32; w++) acc += sRed[w*20 + t];
        g_part1[blockIdx.x*20 + t] = acc;
    }
}

// =====================================================================
// Parallel BN-stats finalize
// =====================================================================
__device__ __forceinline__ void fin_body(const float* __restrict__ part, int nblk,
                                         const float* __restrict__ g,
                                         const float* __restrict__ be,
                                         float* __restrict__ coef)
{
    __shared__ float red[32*20];
    __shared__ float tot[20];
    const int t = threadIdx.x;
    const int c = t % 20, sub = t / 20;
    float acc = 0.f;
    for (int k = sub; k < nblk; k += 32) acc += part[k*20 + c];
    red[sub*20 + c] = acc;
    __syncthreads();
    if (t < 20) {
        float s = 0.f;
        #pragma unroll
        for (int w = 0; w < 32; w++) s += red[w*20 + t];
        tot[t] = s;
    }
    __syncthreads();
    if (t < 10) {
        float mu  = tot[t] / (float)NROWS;
        float var = tot[10 + t] / (float)NROWS - mu*mu;
        float a   = g[t] * rsqrtf(var + EPS_BN);
        coef[t]      = a;
        coef[10 + t] = be[t] - mu*a;
    }
}

__global__ void k_fin1(const float* __restrict__ g1, const float* __restrict__ be1)
{ fin_body(g_part1, NB1, g1, be1, g_coef1); }

__global__ void k_fin2(const float* __restrict__ g2, const float* __restrict__ be2)
{ fin_body(g_part2, NB3, g2, be2, g_coef2); }

// =====================================================================
// Kernel 3: BN1 + relu + GEMM2 + stats2  (float2 I/O)
// =====================================================================
__global__ void __launch_bounds__(TPB) k_mlp2(const float* __restrict__ W2,
                                              const float* __restrict__ b2)
{
    __shared__ float sW2[100], sB2[10], sA[10], sC[10], sRed[(TPB/32)*20];
    const int t = threadIdx.x;
    if (t < 100) sW2[t] = W2[t];
    if (t < 10) { sB2[t] = b2[t]; sA[t] = g_coef1[t]; sC[t] = g_coef1[10+t]; }
    __syncthreads();

    const size_t row = (size_t)blockIdx.x*TPB + t;
    const float2* src2 = (const float2*)(g_h1 + row*10);

    float h[10];
    #pragma unroll
    for (int c = 0; c < 5; c++) {
        float2 v = src2[c];
        h[2*c+0] = fmaxf(fmaf(v.x, sA[2*c+0], sC[2*c+0]), 0.f);
        h[2*c+1] = fmaxf(fmaf(v.y, sA[2*c+1], sC[2*c+1]), 0.f);
    }

    float sum[10], sq[10];
    float2* dst2 = (float2*)(g_h2 + row*10);
    #pragma unroll
    for (int c2 = 0; c2 < 10; c2++) {
        float z = sB2[c2];
        #pragma unroll
        for (int c = 0; c < 10; c++) z = fmaf(h[c], sW2[c*10 + c2], z);
        sum[c2] = z;
        sq[c2]  = z*z;
    }
    #pragma unroll
    for (int c = 0; c < 5; c++) dst2[c] = make_float2(sum[2*c], sum[2*c+1]);

    #pragma unroll
    for (int c = 0; c < 10; c++) {
        #pragma unroll
        for (int o = 16; o > 0; o >>= 1) {
            sum[c] += __shfl_down_sync(0xffffffffu, sum[c], o);
            sq[c]  += __shfl_down_sync(0xffffffffu, sq[c],  o);
        }
    }
    const int warp = t >> 5, lane = t & 31;
    if (lane == 0) {
        #pragma unroll
        for (int c = 0; c < 10; c++) {
            sRed[warp*20 + c]      = sum[c];
            sRed[warp*20 + 10 + c] = sq[c];
        }
    }
    __syncthreads();
    if (t < 20) {
        float acc = 0.f;
        #pragma unroll
        for (int w = 0; w < TPB/32; w++) acc += sRed[w*20 + t];
        g_part2[blockIdx.x*20 + t] = acc;
    }
}

// =====================================================================
// Kernel 5: BN2 + relu + max over k  (float2 I/O)
// =====================================================================
__global__ void __launch_bounds__(TPB) k_out(float* __restrict__ out)
{
    __shared__ float sA[10], sC[10];
    if (threadIdx.x < 10) { sA[threadIdx.x] = g_coef2[threadIdx.x]; sC[threadIdx.x] = g_coef2[10+threadIdx.x]; }
    __syncthreads();

    const size_t p = (size_t)blockIdx.x*TPB + threadIdx.x;
    const float2* src2 = (const float2*)(g_h2 + p*KNN*10);

    float mx[10];
    #pragma unroll
    for (int c = 0; c < 10; c++) mx[c] = 0.f;

    #pragma unroll
    for (int i = 0; i < KNN; i++) {
        #pragma unroll
        for (int c = 0; c < 5; c++) {
            float2 v = src2[i*5 + c];
            mx[2*c+0] = fmaxf(mx[2*c+0], fmaxf(fmaf(v.x, sA[2*c+0], sC[2*c+0]), 0.f));
            mx[2*c+1] = fmaxf(mx[2*c+1], fmaxf(fmaf(v.y, sA[2*c+1], sC[2*c+1]), 0.f));
        }
    }
    float2* o2 = (float2*)(out + p*10);
    #pragma unroll
    for (int c = 0; c < 5; c++) o2[c] = make_float2(mx[2*c], mx[2*c+1]);
}

// =====================================================================
extern "C" void kernel_launch(void* const* d_in, const int* in_sizes, int n_in,
                              void* d_out, int out_size)
{
    const float* x   = (const float*)d_in[0];
    const float* W1  = (const float*)d_in[1];
    const float* b1  = (const float*)d_in[2];
    const float* g1  = (const float*)d_in[3];
    const float* be1 = (const float*)d_in[4];
    const float* W2  = (const float*)d_in[5];
    const float* b2  = (const float*)d_in[6];
    const float* g2  = (const float*)d_in[7];
    const float* be2 = (const float*)d_in[8];
    float* out = (float*)d_out;

    const size_t smemA = (size_t)4*NPTS*sizeof(float)
                       + (size_t)((SPLIT-1)*QPB*10 + QPB)*sizeof(float)
                       + (size_t)(KTPB*QT*CAP + KTPB*QT)*sizeof(int);
    cudaFuncSetAttribute(k_knn, cudaFuncAttributeMaxDynamicSharedMemorySize, (int)smemA);

    k_knn<<<NB1, KTPB, smemA>>>(x);
    k_feat<<<NB1, TPB>>>(x, W1, b1);
    k_fin1<<<1, 640>>>(g1, be1);
    k_mlp2<<<NB3, TPB>>>(W2, b2);
    k_fin2<<<1, 640>>>(g2, be2);
    k_out<<<NPOINTS/TPB, TPB>>>(out);
}